// round 11
// baseline (speedup 1.0000x reference)
#include <cuda_runtime.h>
#include <cstdint>

#define BQ    32
#define NN    512
#define MM    512
#define DFD   64
#define NDIAG 1023
#define NDPAD 1040          // padded (zero) so prefetch never clamps
#define TCH   8             // diagonals per chunk
#define NCHK  128           // chunks: d = 2 .. 1025
#define TI    128           // dist tile rows (i)
#define TJ    128           // dist tile cols (j)
#define HROWS 256           // rows per dp CTA

#define LOG2E 1.4426950408889634f
#define LN2   0.6931471805599453f
#define BIGS  1.4426950408889634e10f   // 1e10 * log2(e): self-maintaining in fp32

// Diagonal-major scaled distances: g_D[b][(i+j)][i] = log2e * ||x_i - y_j||^2.
__device__ float g_D[(size_t)BQ * NDPAD * NN];
// Cross-CTA boundary: g_edge[b][d] = R'[d][256]; g_prog[b] = published counter.
__device__ float g_edge[BQ][1032];
__device__ int   g_prog[BQ];

// ---------------------------------------------------------------------------
__device__ __forceinline__ uint32_t smem_u32(const void* p) {
    return (uint32_t)__cvta_generic_to_shared(p);
}
__device__ __forceinline__ void st_release_cta(uint32_t addr, int v) {
    asm volatile("st.release.cta.shared.b32 [%0], %1;" :: "r"(addr), "r"(v) : "memory");
}
__device__ __forceinline__ int ld_acquire_cta(uint32_t addr) {
    int v;
    asm volatile("ld.acquire.cta.shared.b32 %0, [%1];" : "=r"(v) : "r"(addr) : "memory");
    return v;
}
__device__ __forceinline__ void st_release_gpu(int* p, int v) {
    asm volatile("st.release.gpu.global.b32 [%0], %1;" :: "l"(p), "r"(v) : "memory");
}
__device__ __forceinline__ int ld_acquire_gpu(const int* p) {
    int v;
    asm volatile("ld.acquire.gpu.global.b32 %0, [%1];" : "=r"(v) : "l"(p) : "memory");
    return v;
}
__device__ __forceinline__ float ldg_cg(const float* p) {   // L1-bypass load
    float v;
    asm volatile("ld.global.cg.f32 %0, [%1];" : "=f"(v) : "l"(p) : "memory");
    return v;
}
__device__ __forceinline__ float ex2(float x) {
    float r; asm("ex2.approx.f32 %0, %1;" : "=f"(r) : "f"(x)); return r;
}
__device__ __forceinline__ float lg2(float x) {
    float r; asm("lg2.approx.f32 %0, %1;" : "=f"(r) : "f"(x)); return r;
}

// ---------------------------------------------------------------------------
// Kernel 1: pairwise squared distances (Gram form), scaled by log2e,
// diagonal-major output. 128x128 tile per CTA, 8x8 register tile per thread.
// Also resets the dp cross-CTA handoff state (runs before dp in-stream).
// ---------------------------------------------------------------------------
__global__ void dist_kernel(const float* __restrict__ X,
                            const float* __restrict__ Y) {
    extern __shared__ float sm[];      // Xs|Ys, reused as Dt
    __shared__ float xx[TI], yy[TJ];
    float* Xs = sm;                    // [128][65]
    float* Ys = sm + TI * 65;          // [128][65]

    const int b  = blockIdx.z;
    const int i0 = blockIdx.y * TI;
    const int j0 = blockIdx.x * TJ;
    const int tid = threadIdx.x;

    // Per-launch reset of dp handoff state.
    if (blockIdx.x == 0 && blockIdx.y == 0 && tid == 0) {
        g_prog[b] = 1;
        g_edge[b][0] = BIGS;
        g_edge[b][1] = BIGS;
    }

    const float4* Xb = (const float4*)(X + ((size_t)b * NN + i0) * DFD);
    const float4* Yb = (const float4*)(Y + ((size_t)b * MM + j0) * DFD);

    #pragma unroll
    for (int idx = tid; idx < TI * 16; idx += 256) {
        int r = idx >> 4, c4 = idx & 15;
        float4 v = Xb[r * 16 + c4];
        float* dst = &Xs[r * 65 + c4 * 4];
        dst[0] = v.x; dst[1] = v.y; dst[2] = v.z; dst[3] = v.w;
    }
    #pragma unroll
    for (int idx = tid; idx < TJ * 16; idx += 256) {
        int r = idx >> 4, c4 = idx & 15;
        float4 v = Yb[r * 16 + c4];
        float* dst = &Ys[r * 65 + c4 * 4];
        dst[0] = v.x; dst[1] = v.y; dst[2] = v.z; dst[3] = v.w;
    }
    __syncthreads();

    if (tid < TI + TJ) {
        const float* row = (tid < TI) ? &Xs[tid * 65] : &Ys[(tid - TI) * 65];
        float s = 0.f;
        #pragma unroll 8
        for (int k = 0; k < DFD; k++) s = fmaf(row[k], row[k], s);
        s *= LOG2E;
        if (tid < TI) xx[tid] = s; else yy[tid - TI] = s;
    }
    __syncthreads();

    const int tx = tid & 15;
    const int ty = tid >> 4;

    float acc[8][8];
    #pragma unroll
    for (int u = 0; u < 8; u++)
        #pragma unroll
        for (int v = 0; v < 8; v++) acc[u][v] = 0.f;

    #pragma unroll 2
    for (int k = 0; k < DFD; k++) {
        float xa[8], yb[8];
        #pragma unroll
        for (int u = 0; u < 8; u++) xa[u] = Xs[(ty + 16 * u) * 65 + k];
        #pragma unroll
        for (int v = 0; v < 8; v++) yb[v] = Ys[(tx + 16 * v) * 65 + k];
        #pragma unroll
        for (int u = 0; u < 8; u++)
            #pragma unroll
            for (int v = 0; v < 8; v++)
                acc[u][v] = fmaf(xa[u], yb[v], acc[u][v]);
    }
    __syncthreads();

    float* Dt = sm;                    // pitch 130 -> conflict-free diagonals
    #pragma unroll
    for (int u = 0; u < 8; u++) {
        const float xv = xx[ty + 16 * u];
        #pragma unroll
        for (int v = 0; v < 8; v++)
            Dt[(ty + 16 * u) * 130 + (tx + 16 * v)] =
                fmaf(-2.0f * LOG2E, acc[u][v], xv + yy[tx + 16 * v]);
    }
    __syncthreads();

    const int warp = tid >> 5, lane = tid & 31;
    const size_t base = (size_t)b * NDPAD * NN;
    for (int dl = warp; dl < TI + TJ - 1; dl += 8) {
        int lo = dl - (TJ - 1); if (lo < 0) lo = 0;
        int hi = dl;            if (hi > TI - 1) hi = TI - 1;
        for (int ii = lo + lane; ii <= hi; ii += 32) {
            int gi = i0 + ii;
            int gj = j0 + dl - ii;
            g_D[base + (size_t)(gi + gj) * NN + gi] = Dt[ii * 130 + (dl - ii)];
        }
    }
}

// ---------------------------------------------------------------------------
// Soft-min cell, log2 domain, (p,q) presorted, late input last.
// ---------------------------------------------------------------------------
__device__ __forceinline__ float cell(float p, float q, float late, float Dv) {
    const float m   = fminf(p, late);
    const float mid = fminf(q, fmaxf(p, late));
    const float top = fmaxf(q, late);
    const float s   = 1.0f + ex2(m - mid) + ex2(m - top);
    return Dv + m - lg2(s);
}

// ---------------------------------------------------------------------------
// Kernel 2: warp-pipelined wavefront, 2 CTAs per batch, 256 rows each,
// ONE row per thread (8 warps x 32 rows per CTA -> 2 warps/SMSP).
// Intra-CTA: SMEM lane ring + edge history + monotonic smem counters.
// Inter-CTA (row-256 boundary): STG edges + release/acquire global counter;
// consumer reads edges with L1-bypass loads. Capture chunk hoisted.
// ---------------------------------------------------------------------------
__global__ void __launch_bounds__(HROWS, 1)
dp_kernel(const int* __restrict__ X_len, const int* __restrict__ Y_len,
          float* __restrict__ out) {
    __shared__ float edge[8][1032];    // edge[w][d] = R'[d][base + 32(w+1)]
    __shared__ float nb[8][32];        // per-warp lane ring
    __shared__ int   prog[8];

    const int cta  = blockIdx.x;
    const int b    = cta >> 1;
    const int half = cta & 1;
    const int tid  = threadIdx.x;
    const int w    = tid >> 5;
    const int lane = tid & 31;
    const int i    = half * HROWS + tid + 1;   // owned row

    const int xl  = X_len[b];
    const int tot = xl + Y_len[b];
    const bool want  = (xl == i);
    const bool isl0  = (lane == 0);
    const bool isl31 = (lane == 31);
    const int  nlane = (lane == 0) ? 31 : lane - 1;
    const bool gcons = (half == 1) && (w == 0);               // global consumer
    const bool gp31  = (half == 0) && (w == 7) && isl31;      // global producer

    if (tid < 16) edge[tid >> 1][tid & 1] = BIGS;
    if (tid < 8)  prog[tid] = 1;
    nb[w][lane] = BIGS;
    __syncthreads();                    // the only CTA barrier

    const uint32_t prog_self = smem_u32(&prog[w]);
    const uint32_t prog_prev = smem_u32(&prog[(w == 0) ? 0 : w - 1]);

    const float* Dp = g_D + (size_t)b * NDPAD * NN + half * HROWS + tid;

    float Dc[TCH];
    #pragma unroll
    for (int k = 0; k < TCH; ++k) Dc[k] = Dp[(size_t)k * NN];

    float p = (tid == 0 && half == 0) ? 0.0f : BIGS;
    float q = BIGS;
    float res = 0.0f;

    for (int c = 0; c < NCHK; ++c) {
        const int d0 = 2 + TCH * c;

        // Prefetch next chunk's D (padded slots; tail reads hit zero pad).
        float Dn[TCH];
        #pragma unroll
        for (int k = 0; k < TCH; ++k)
            Dn[k] = Dp[(size_t)(TCH * (c + 1) + k) * NN];

        // Acquire producer edges for this chunk.
        float e[TCH];
        const int needed = d0 + TCH - 2;
        if (w > 0) {
            while (ld_acquire_cta(prog_prev) < needed) __nanosleep(64);
            #pragma unroll
            for (int k = 0; k < TCH; ++k) e[k] = edge[w - 1][d0 - 1 + k];
        } else if (gcons) {
            while (ld_acquire_gpu(&g_prog[b]) < needed) __nanosleep(128);
            #pragma unroll
            for (int k = 0; k < TCH; ++k) e[k] = ldg_cg(&g_edge[b][d0 - 1 + k]);
        } else {
            #pragma unroll
            for (int k = 0; k < TCH; ++k) e[k] = BIGS;
        }

        if ((unsigned)(tot - d0) < TCH) {
            // ---- capture body ----
            #pragma unroll
            for (int k = 0; k < TCH; ++k) {
                const int d = d0 + k;
                const float nbv = nb[w][nlane];
                const float tmp = isl0 ? e[k] : nbv;

                const float cur = cell(p, q, tmp, Dc[k]);

                nb[w][lane] = cur;
                if (isl31) edge[w][d] = cur;
                if (gp31)  g_edge[b][d] = cur;
                if (d == tot) res = want ? cur : res;

                p = fminf(tmp, cur);
                q = fmaxf(tmp, cur);
            }
        } else {
            // ---- hot body ----
            #pragma unroll
            for (int k = 0; k < TCH; ++k) {
                const int d = d0 + k;
                const float nbv = nb[w][nlane];
                const float tmp = isl0 ? e[k] : nbv;

                const float cur = cell(p, q, tmp, Dc[k]);

                nb[w][lane] = cur;
                if (isl31) edge[w][d] = cur;
                if (gp31)  g_edge[b][d] = cur;

                p = fminf(tmp, cur);
                q = fmaxf(tmp, cur);
            }
        }

        if (w < 7 && isl31)
            st_release_cta(prog_self, d0 + TCH - 1);   // orders edge STS
        if (gp31)
            st_release_gpu(&g_prog[b], d0 + TCH - 1);  // orders edge STGs

        #pragma unroll
        for (int k = 0; k < TCH; ++k) Dc[k] = Dn[k];
    }

    if (want) out[b] = res * LN2;
}

// ---------------------------------------------------------------------------
extern "C" void kernel_launch(void* const* d_in, const int* in_sizes, int n_in,
                              void* d_out, int out_size) {
    const float* X     = (const float*)d_in[0];
    const float* Y     = (const float*)d_in[1];
    const int*   X_len = (const int*)d_in[2];
    const int*   Y_len = (const int*)d_in[3];
    float*       out   = (float*)d_out;

    const int dist_smem = (TI * 65 + TJ * 65) * 4;   // 66560 B
    static bool attr_set = false;
    if (!attr_set) {
        cudaFuncSetAttribute(dist_kernel,
                             cudaFuncAttributeMaxDynamicSharedMemorySize,
                             dist_smem);
        attr_set = true;
    }

    dist_kernel<<<dim3(MM / TJ, NN / TI, BQ), 256, dist_smem>>>(X, Y);
    dp_kernel<<<BQ * 2, HROWS>>>(X_len, Y_len, out);
}

// round 12
// speedup vs baseline: 1.2762x; 1.2762x over previous
#include <cuda_runtime.h>
#include <cstdint>

#define BQ    32
#define NN    512
#define MM    512
#define DFD   64
#define NDIAG 1023
#define NDPAD 1040          // padded (zero) so prefetch never clamps
#define TCH   8             // diagonals per chunk
#define NCHK  128           // chunks: d = 2 .. 1025
#define TI    128           // dist tile rows (i)
#define TJ    128           // dist tile cols (j)
#define HROWS 256           // rows per dp CTA

#define LOG2E 1.4426950408889634f
#define LN2   0.6931471805599453f
#define BIGS  1.4426950408889634e10f   // 1e10 * log2(e): self-maintaining in fp32

// Diagonal-major scaled distances: g_D[b][(i+j)][i] = log2e * ||x_i - y_j||^2.
__device__ float g_D[(size_t)BQ * NDPAD * NN];

// ---------------------------------------------------------------------------
__device__ __forceinline__ uint32_t smem_u32(const void* p) {
    return (uint32_t)__cvta_generic_to_shared(p);
}
__device__ __forceinline__ void st_release_cta(uint32_t addr, int v) {
    asm volatile("st.release.cta.shared.b32 [%0], %1;" :: "r"(addr), "r"(v) : "memory");
}
__device__ __forceinline__ int ld_acquire_cta(uint32_t addr) {
    int v;
    asm volatile("ld.acquire.cta.shared.b32 %0, [%1];" : "=r"(v) : "r"(addr) : "memory");
    return v;
}
// --- cluster / DSMEM primitives ---
__device__ __forceinline__ uint32_t cluster_rank() {
    uint32_t r; asm("mov.u32 %0, %%cluster_ctarank;" : "=r"(r)); return r;
}
__device__ __forceinline__ uint32_t mapa_cluster(uint32_t laddr, uint32_t rank) {
    uint32_t r;
    asm("mapa.shared::cluster.u32 %0, %1, %2;" : "=r"(r) : "r"(laddr), "r"(rank));
    return r;
}
__device__ __forceinline__ void st_cluster_f32(uint32_t addr, float v) {
    asm volatile("st.shared::cluster.f32 [%0], %1;" :: "r"(addr), "f"(v) : "memory");
}
__device__ __forceinline__ void st_release_cluster(uint32_t addr, int v) {
    asm volatile("st.release.cluster.shared::cluster.b32 [%0], %1;"
                 :: "r"(addr), "r"(v) : "memory");
}
__device__ __forceinline__ int ld_acquire_cluster(uint32_t addr) {
    int v;
    asm volatile("ld.acquire.cluster.shared::cta.b32 %0, [%1];"
                 : "=r"(v) : "r"(addr) : "memory");
    return v;
}
__device__ __forceinline__ void cluster_sync() {
    asm volatile("barrier.cluster.arrive.aligned;" ::: "memory");
    asm volatile("barrier.cluster.wait.aligned;" ::: "memory");
}
__device__ __forceinline__ float ex2(float x) {
    float r; asm("ex2.approx.f32 %0, %1;" : "=f"(r) : "f"(x)); return r;
}
__device__ __forceinline__ float lg2(float x) {
    float r; asm("lg2.approx.f32 %0, %1;" : "=f"(r) : "f"(x)); return r;
}

// ---------------------------------------------------------------------------
// Kernel 1: pairwise squared distances (Gram form), scaled by log2e,
// diagonal-major output. 128x128 tile per CTA, 8x8 register tile per thread.
// ---------------------------------------------------------------------------
__global__ void dist_kernel(const float* __restrict__ X,
                            const float* __restrict__ Y) {
    extern __shared__ float sm[];      // Xs|Ys, reused as Dt
    __shared__ float xx[TI], yy[TJ];
    float* Xs = sm;                    // [128][65]
    float* Ys = sm + TI * 65;          // [128][65]

    const int b  = blockIdx.z;
    const int i0 = blockIdx.y * TI;
    const int j0 = blockIdx.x * TJ;
    const int tid = threadIdx.x;

    const float4* Xb = (const float4*)(X + ((size_t)b * NN + i0) * DFD);
    const float4* Yb = (const float4*)(Y + ((size_t)b * MM + j0) * DFD);

    #pragma unroll
    for (int idx = tid; idx < TI * 16; idx += 256) {
        int r = idx >> 4, c4 = idx & 15;
        float4 v = Xb[r * 16 + c4];
        float* dst = &Xs[r * 65 + c4 * 4];
        dst[0] = v.x; dst[1] = v.y; dst[2] = v.z; dst[3] = v.w;
    }
    #pragma unroll
    for (int idx = tid; idx < TJ * 16; idx += 256) {
        int r = idx >> 4, c4 = idx & 15;
        float4 v = Yb[r * 16 + c4];
        float* dst = &Ys[r * 65 + c4 * 4];
        dst[0] = v.x; dst[1] = v.y; dst[2] = v.z; dst[3] = v.w;
    }
    __syncthreads();

    if (tid < TI + TJ) {
        const float* row = (tid < TI) ? &Xs[tid * 65] : &Ys[(tid - TI) * 65];
        float s = 0.f;
        #pragma unroll 8
        for (int k = 0; k < DFD; k++) s = fmaf(row[k], row[k], s);
        s *= LOG2E;
        if (tid < TI) xx[tid] = s; else yy[tid - TI] = s;
    }
    __syncthreads();

    const int tx = tid & 15;
    const int ty = tid >> 4;

    float acc[8][8];
    #pragma unroll
    for (int u = 0; u < 8; u++)
        #pragma unroll
        for (int v = 0; v < 8; v++) acc[u][v] = 0.f;

    #pragma unroll 2
    for (int k = 0; k < DFD; k++) {
        float xa[8], yb[8];
        #pragma unroll
        for (int u = 0; u < 8; u++) xa[u] = Xs[(ty + 16 * u) * 65 + k];
        #pragma unroll
        for (int v = 0; v < 8; v++) yb[v] = Ys[(tx + 16 * v) * 65 + k];
        #pragma unroll
        for (int u = 0; u < 8; u++)
            #pragma unroll
            for (int v = 0; v < 8; v++)
                acc[u][v] = fmaf(xa[u], yb[v], acc[u][v]);
    }
    __syncthreads();

    float* Dt = sm;                    // pitch 130 -> conflict-free diagonals
    #pragma unroll
    for (int u = 0; u < 8; u++) {
        const float xv = xx[ty + 16 * u];
        #pragma unroll
        for (int v = 0; v < 8; v++)
            Dt[(ty + 16 * u) * 130 + (tx + 16 * v)] =
                fmaf(-2.0f * LOG2E, acc[u][v], xv + yy[tx + 16 * v]);
    }
    __syncthreads();

    const int warp = tid >> 5, lane = tid & 31;
    const size_t base = (size_t)b * NDPAD * NN;
    for (int dl = warp; dl < TI + TJ - 1; dl += 8) {
        int lo = dl - (TJ - 1); if (lo < 0) lo = 0;
        int hi = dl;            if (hi > TI - 1) hi = TI - 1;
        for (int ii = lo + lane; ii <= hi; ii += 32) {
            int gi = i0 + ii;
            int gj = j0 + dl - ii;
            g_D[base + (size_t)(gi + gj) * NN + gi] = Dt[ii * 130 + (dl - ii)];
        }
    }
}

// ---------------------------------------------------------------------------
// Soft-min cell, log2 domain, (p,q) presorted, late input last.
// ---------------------------------------------------------------------------
__device__ __forceinline__ float cell(float p, float q, float late, float Dv) {
    const float m   = fminf(p, late);
    const float mid = fminf(q, fmaxf(p, late));
    const float top = fmaxf(q, late);
    const float s   = 1.0f + ex2(m - mid) + ex2(m - top);
    return Dv + m - lg2(s);
}

// ---------------------------------------------------------------------------
// Kernel 2: warp-pipelined wavefront, cluster of 2 CTAs per batch.
// Each CTA: 256 threads = 8 warps x 32 rows, ONE row per thread.
// Intra-CTA: SMEM lane ring + edge history + monotonic smem counters.
// Inter-CTA (row-256 boundary): producer pushes edges into the consumer's
// SMEM inbox via DSMEM stores + cluster-scope release counter; consumer
// polls its LOCAL counter (LDS-latency, no L2 round trip).
// ---------------------------------------------------------------------------
__global__ void __cluster_dims__(2, 1, 1) __launch_bounds__(HROWS, 1)
dp_kernel(const int* __restrict__ X_len, const int* __restrict__ Y_len,
          float* __restrict__ out) {
    __shared__ float edge[8][1032];    // edge[w][d] = R'[d][base + 32(w+1)]
    __shared__ float nb[8][32];        // per-warp lane ring
    __shared__ int   prog[8];
    __shared__ float xedge[1032];      // cross-CTA inbox (rank1 local)
    __shared__ int   xprog;

    const int cta  = blockIdx.x;
    const int b    = cta >> 1;
    const int half = cta & 1;          // == cluster_ctarank()
    const int tid  = threadIdx.x;
    const int w    = tid >> 5;
    const int lane = tid & 31;
    const int i    = half * HROWS + tid + 1;   // owned row

    const int xl  = X_len[b];
    const int tot = xl + Y_len[b];
    const bool want  = (xl == i);
    const bool isl0  = (lane == 0);
    const bool isl31 = (lane == 31);
    const int  nlane = (lane == 0) ? 31 : lane - 1;
    const bool gcons = (half == 1) && (w == 0);               // inbox consumer
    const bool gp31  = (half == 0) && (w == 7) && isl31;      // inbox producer

    if (tid < 16) edge[tid >> 1][tid & 1] = BIGS;
    if (tid < 8)  prog[tid] = 1;
    if (tid == 0) { xprog = 1; xedge[0] = BIGS; xedge[1] = BIGS; }
    nb[w][lane] = BIGS;
    __syncthreads();
    cluster_sync();                    // inbox init visible before DSMEM writes

    const uint32_t prog_self = smem_u32(&prog[w]);
    const uint32_t prog_prev = smem_u32(&prog[(w == 0) ? 0 : w - 1]);
    const uint32_t xprog_loc = smem_u32(&xprog);
    // Producer: peer (rank 1) addresses of the inbox.
    const uint32_t xedge_peer = mapa_cluster(smem_u32(&xedge[0]), 1);
    const uint32_t xprog_peer = mapa_cluster(xprog_loc, 1);

    const float* Dp = g_D + (size_t)b * NDPAD * NN + half * HROWS + tid;

    float Dc[TCH];
    #pragma unroll
    for (int k = 0; k < TCH; ++k) Dc[k] = Dp[(size_t)k * NN];

    float p = (tid == 0 && half == 0) ? 0.0f : BIGS;
    float q = BIGS;
    float res = 0.0f;

    for (int c = 0; c < NCHK; ++c) {
        const int d0 = 2 + TCH * c;

        // Prefetch next chunk's D (padded slots; tail reads hit zero pad).
        float Dn[TCH];
        #pragma unroll
        for (int k = 0; k < TCH; ++k)
            Dn[k] = Dp[(size_t)(TCH * (c + 1) + k) * NN];

        // Acquire producer edges for this chunk.
        float e[TCH];
        const int needed = d0 + TCH - 2;
        if (w > 0) {
            while (ld_acquire_cta(prog_prev) < needed) __nanosleep(64);
            #pragma unroll
            for (int k = 0; k < TCH; ++k) e[k] = edge[w - 1][d0 - 1 + k];
        } else if (gcons) {
            while (ld_acquire_cluster(xprog_loc) < needed) __nanosleep(64);
            #pragma unroll
            for (int k = 0; k < TCH; ++k) e[k] = xedge[d0 - 1 + k];
        } else {
            #pragma unroll
            for (int k = 0; k < TCH; ++k) e[k] = BIGS;
        }

        float ed[TCH];   // boundary stash (producer lane only meaningful)

        if ((unsigned)(tot - d0) < TCH) {
            // ---- capture body ----
            #pragma unroll
            for (int k = 0; k < TCH; ++k) {
                const int d = d0 + k;
                const float nbv = nb[w][nlane];
                const float tmp = isl0 ? e[k] : nbv;

                const float cur = cell(p, q, tmp, Dc[k]);

                nb[w][lane] = cur;
                if (isl31) edge[w][d] = cur;
                ed[k] = cur;
                if (d == tot) res = want ? cur : res;

                p = fminf(tmp, cur);
                q = fmaxf(tmp, cur);
            }
        } else {
            // ---- hot body ----
            #pragma unroll
            for (int k = 0; k < TCH; ++k) {
                const int d = d0 + k;
                const float nbv = nb[w][nlane];
                const float tmp = isl0 ? e[k] : nbv;

                const float cur = cell(p, q, tmp, Dc[k]);

                nb[w][lane] = cur;
                if (isl31) edge[w][d] = cur;
                ed[k] = cur;

                p = fminf(tmp, cur);
                q = fmaxf(tmp, cur);
            }
        }

        if (w < 7 && isl31)
            st_release_cta(prog_self, d0 + TCH - 1);   // orders edge STS
        if (gp31) {
            #pragma unroll
            for (int k = 0; k < TCH; ++k)
                st_cluster_f32(xedge_peer + (uint32_t)(d0 + k) * 4, ed[k]);
            st_release_cluster(xprog_peer, d0 + TCH - 1);  // orders DSMEM sts
        }

        #pragma unroll
        for (int k = 0; k < TCH; ++k) Dc[k] = Dn[k];
    }

    if (want) out[b] = res * LN2;

    cluster_sync();                    // keep peer SMEM alive until drained
}

// ---------------------------------------------------------------------------
extern "C" void kernel_launch(void* const* d_in, const int* in_sizes, int n_in,
                              void* d_out, int out_size) {
    const float* X     = (const float*)d_in[0];
    const float* Y     = (const float*)d_in[1];
    const int*   X_len = (const int*)d_in[2];
    const int*   Y_len = (const int*)d_in[3];
    float*       out   = (float*)d_out;

    const int dist_smem = (TI * 65 + TJ * 65) * 4;   // 66560 B
    static bool attr_set = false;
    if (!attr_set) {
        cudaFuncSetAttribute(dist_kernel,
                             cudaFuncAttributeMaxDynamicSharedMemorySize,
                             dist_smem);
        attr_set = true;
    }

    dist_kernel<<<dim3(MM / TJ, NN / TI, BQ), 256, dist_smem>>>(X, Y);
    dp_kernel<<<BQ * 2, HROWS>>>(X_len, Y_len, out);
}

// round 13
// speedup vs baseline: 1.7833x; 1.3973x over previous
#include <cuda_runtime.h>
#include <cstdint>

#define BQ    32
#define NN    512
#define MM    512
#define DFD   64
#define NDIAG 1023
#define NDPAD 1040          // padded (zero) so prefetch never clamps
#define TCH   8             // diagonals per chunk
#define TI    128           // dist tile rows (i)
#define TJ    128           // dist tile cols (j)
#define CPW   72            // active chunks per warp (trapezoid skip)

#define LOG2E 1.4426950408889634f
#define LN2   0.6931471805599453f
#define BIGS  1.4426950408889634e10f   // 1e10 * log2(e): self-maintaining in fp32
#define PROG_INF 100000

// Diagonal-major scaled distances: g_D[b][(i+j)][i] = log2e * ||x_i - y_j||^2.
// Zero-initialized; positions outside the valid band are never written.
__device__ float g_D[(size_t)BQ * NDPAD * NN];

// ---------------------------------------------------------------------------
__device__ __forceinline__ uint32_t smem_u32(const void* p) {
    return (uint32_t)__cvta_generic_to_shared(p);
}
__device__ __forceinline__ void st_release_cta(uint32_t addr, int v) {
    asm volatile("st.release.cta.shared.b32 [%0], %1;" :: "r"(addr), "r"(v) : "memory");
}
__device__ __forceinline__ int ld_acquire_cta(uint32_t addr) {
    int v;
    asm volatile("ld.acquire.cta.shared.b32 %0, [%1];" : "=r"(v) : "r"(addr) : "memory");
    return v;
}
__device__ __forceinline__ float ex2(float x) {
    float r; asm("ex2.approx.f32 %0, %1;" : "=f"(r) : "f"(x)); return r;
}
__device__ __forceinline__ float lg2(float x) {
    float r; asm("lg2.approx.f32 %0, %1;" : "=f"(r) : "f"(x)); return r;
}

// ---------------------------------------------------------------------------
// Kernel 1: pairwise squared distances (Gram form), scaled by log2e,
// diagonal-major output. 128x128 tile per CTA, 8x8 register tile per thread.
// ---------------------------------------------------------------------------
__global__ void dist_kernel(const float* __restrict__ X,
                            const float* __restrict__ Y) {
    extern __shared__ float sm[];      // Xs|Ys, reused as Dt
    __shared__ float xx[TI], yy[TJ];
    float* Xs = sm;                    // [128][65]
    float* Ys = sm + TI * 65;          // [128][65]

    const int b  = blockIdx.z;
    const int i0 = blockIdx.y * TI;
    const int j0 = blockIdx.x * TJ;
    const int tid = threadIdx.x;

    const float4* Xb = (const float4*)(X + ((size_t)b * NN + i0) * DFD);
    const float4* Yb = (const float4*)(Y + ((size_t)b * MM + j0) * DFD);

    #pragma unroll
    for (int idx = tid; idx < TI * 16; idx += 256) {
        int r = idx >> 4, c4 = idx & 15;
        float4 v = Xb[r * 16 + c4];
        float* dst = &Xs[r * 65 + c4 * 4];
        dst[0] = v.x; dst[1] = v.y; dst[2] = v.z; dst[3] = v.w;
    }
    #pragma unroll
    for (int idx = tid; idx < TJ * 16; idx += 256) {
        int r = idx >> 4, c4 = idx & 15;
        float4 v = Yb[r * 16 + c4];
        float* dst = &Ys[r * 65 + c4 * 4];
        dst[0] = v.x; dst[1] = v.y; dst[2] = v.z; dst[3] = v.w;
    }
    __syncthreads();

    if (tid < TI + TJ) {
        const float* row = (tid < TI) ? &Xs[tid * 65] : &Ys[(tid - TI) * 65];
        float s = 0.f;
        #pragma unroll 8
        for (int k = 0; k < DFD; k++) s = fmaf(row[k], row[k], s);
        s *= LOG2E;
        if (tid < TI) xx[tid] = s; else yy[tid - TI] = s;
    }
    __syncthreads();

    const int tx = tid & 15;
    const int ty = tid >> 4;

    float acc[8][8];
    #pragma unroll
    for (int u = 0; u < 8; u++)
        #pragma unroll
        for (int v = 0; v < 8; v++) acc[u][v] = 0.f;

    #pragma unroll 2
    for (int k = 0; k < DFD; k++) {
        float xa[8], yb[8];
        #pragma unroll
        for (int u = 0; u < 8; u++) xa[u] = Xs[(ty + 16 * u) * 65 + k];
        #pragma unroll
        for (int v = 0; v < 8; v++) yb[v] = Ys[(tx + 16 * v) * 65 + k];
        #pragma unroll
        for (int u = 0; u < 8; u++)
            #pragma unroll
            for (int v = 0; v < 8; v++)
                acc[u][v] = fmaf(xa[u], yb[v], acc[u][v]);
    }
    __syncthreads();

    float* Dt = sm;                    // pitch 130 -> conflict-free diagonals
    #pragma unroll
    for (int u = 0; u < 8; u++) {
        const float xv = xx[ty + 16 * u];
        #pragma unroll
        for (int v = 0; v < 8; v++)
            Dt[(ty + 16 * u) * 130 + (tx + 16 * v)] =
                fmaf(-2.0f * LOG2E, acc[u][v], xv + yy[tx + 16 * v]);
    }
    __syncthreads();

    const int warp = tid >> 5, lane = tid & 31;
    const size_t base = (size_t)b * NDPAD * NN;
    for (int dl = warp; dl < TI + TJ - 1; dl += 8) {
        int lo = dl - (TJ - 1); if (lo < 0) lo = 0;
        int hi = dl;            if (hi > TI - 1) hi = TI - 1;
        for (int ii = lo + lane; ii <= hi; ii += 32) {
            int gi = i0 + ii;
            int gj = j0 + dl - ii;
            g_D[base + (size_t)(gi + gj) * NN + gi] = Dt[ii * 130 + (dl - ii)];
        }
    }
}

// ---------------------------------------------------------------------------
// Soft-min cell, log2 domain, (p,q) presorted, late input last.
// ---------------------------------------------------------------------------
__device__ __forceinline__ float cell(float p, float q, float late, float Dv) {
    const float m   = fminf(p, late);
    const float mid = fminf(q, fmaxf(p, late));
    const float top = fmaxf(q, late);
    const float s   = 1.0f + ex2(m - mid) + ex2(m - top);
    return Dv + m - lg2(s);
}

// ---------------------------------------------------------------------------
// Kernel 2: warp-pipelined wavefront with TRAPEZOID SKIP. One CTA per batch;
// 8 warps x 64 rows (thread t owns rows 2t+1, 2t+2). Warp w only processes
// its active chunks [8w, 8w+71] (valid d in [64w+2, 64w+576]); outside that
// range its cells are BIGS, provided by the pre-initialized edge array.
// Producer publishes per-chunk monotonic counters, then PROG_INF after its
// last chunk so trailing consumers never deadlock.
// ---------------------------------------------------------------------------
__global__ void __launch_bounds__(256, 1)
dp_kernel(const int* __restrict__ X_len, const int* __restrict__ Y_len,
          float* __restrict__ out) {
    __shared__ float edge[8][1032];    // edge[w][d] = R'[d][64(w+1)]
    __shared__ float nb[8][32];        // per-warp lane ring of cur_hi
    __shared__ int   prog[8];

    const int b    = blockIdx.x;
    const int tid  = threadIdx.x;
    const int w    = tid >> 5;
    const int lane = tid & 31;
    const int i_lo = 2 * tid + 1;
    const int i_hi = i_lo + 1;

    const int xl  = X_len[b];
    const int tot = xl + Y_len[b];
    const bool wantlo = (xl == i_lo);
    const bool wanthi = (xl == i_hi);
    const bool isl0   = (lane == 0);
    const bool isl31  = (lane == 31);
    const int  nlane  = (lane == 0) ? 31 : lane - 1;

    // Pre-init the ENTIRE edge history to BIGS (covers never-written slots).
    for (int idx = tid; idx < 8 * 1032; idx += 256)
        ((float*)edge)[idx] = BIGS;
    if (tid < 8) prog[tid] = 1;
    nb[w][lane] = BIGS;
    __syncthreads();                    // the only CTA barrier

    const uint32_t prog_self = smem_u32(&prog[w]);
    const uint32_t prog_prev = smem_u32(&prog[(w == 0) ? 0 : w - 1]);

    const float2* Dp = (const float2*)(g_D + (size_t)b * NDPAD * NN) + tid;

    // Active chunk range for this warp.
    const int c0 = 8 * w;
    const int c1 = 8 * w + CPW - 1;

    float2 Dc[TCH];
    #pragma unroll
    for (int k = 0; k < TCH; ++k)
        Dc[k] = Dp[(size_t)(TCH * c0 + k) * 256];

    float r1_lo = BIGS, r1_hi = BIGS;
    float p_lo = (tid == 0) ? 0.0f : BIGS, q_lo = BIGS;
    float p_hi = BIGS, q_hi = BIGS;
    float res = 0.0f;

    for (int c = c0; c <= c1; ++c) {
        const int d0 = 2 + TCH * c;

        // Prefetch next chunk's D (padded slots; tail reads hit zero pad).
        float2 Dn[TCH];
        #pragma unroll
        for (int k = 0; k < TCH; ++k)
            Dn[k] = Dp[(size_t)(TCH * (c + 1) + k) * 256];

        // Acquire producer edges for this chunk (monotonic counter, backoff).
        float e[TCH];
        if (w > 0) {
            const int needed = d0 + TCH - 2;
            while (ld_acquire_cta(prog_prev) < needed) __nanosleep(64);
            #pragma unroll
            for (int k = 0; k < TCH; ++k) e[k] = edge[w - 1][d0 - 1 + k];
        } else {
            #pragma unroll
            for (int k = 0; k < TCH; ++k) e[k] = BIGS;
        }

        if ((unsigned)(tot - d0) < TCH) {
            // ---- capture body: the one chunk that can produce the output ----
            #pragma unroll
            for (int k = 0; k < TCH; ++k) {
                const int d = d0 + k;
                const float nbv = nb[w][nlane];

                const float cur_hi = cell(p_hi, q_hi, r1_hi, Dc[k].y);
                nb[w][lane] = cur_hi;
                if (isl31) edge[w][d] = cur_hi;

                const float tmp = isl0 ? e[k] : nbv;
                const float cur_lo = cell(p_lo, q_lo, tmp, Dc[k].x);

                if (d == tot)
                    res = wantlo ? cur_lo : (wanthi ? cur_hi : res);

                p_hi = fminf(r1_lo, cur_lo);
                q_hi = fmaxf(r1_lo, cur_lo);
                p_lo = fminf(tmp, cur_lo);
                q_lo = fmaxf(tmp, cur_lo);
                r1_lo = cur_lo;
                r1_hi = cur_hi;
            }
        } else {
            // ---- hot body ----
            #pragma unroll
            for (int k = 0; k < TCH; ++k) {
                const int d = d0 + k;
                const float nbv = nb[w][nlane];

                const float cur_hi = cell(p_hi, q_hi, r1_hi, Dc[k].y);
                nb[w][lane] = cur_hi;
                if (isl31) edge[w][d] = cur_hi;

                const float tmp = isl0 ? e[k] : nbv;
                const float cur_lo = cell(p_lo, q_lo, tmp, Dc[k].x);

                p_hi = fminf(r1_lo, cur_lo);
                q_hi = fmaxf(r1_lo, cur_lo);
                p_lo = fminf(tmp, cur_lo);
                q_lo = fmaxf(tmp, cur_lo);
                r1_lo = cur_lo;
                r1_hi = cur_hi;
            }
        }

        if (w < 7 && isl31)
            st_release_cta(prog_self, d0 + TCH - 1);   // orders edge STS

        #pragma unroll
        for (int k = 0; k < TCH; ++k) Dc[k] = Dn[k];
    }

    // Final publish: everything beyond this warp's active range is BIGS
    // (pre-initialized) — release "infinity" so consumers never wait.
    if (w < 7 && isl31)
        st_release_cta(prog_self, PROG_INF);

    if (wantlo | wanthi) out[b] = res * LN2;
}

// ---------------------------------------------------------------------------
extern "C" void kernel_launch(void* const* d_in, const int* in_sizes, int n_in,
                              void* d_out, int out_size) {
    const float* X     = (const float*)d_in[0];
    const float* Y     = (const float*)d_in[1];
    const int*   X_len = (const int*)d_in[2];
    const int*   Y_len = (const int*)d_in[3];
    float*       out   = (float*)d_out;

    const int dist_smem = (TI * 65 + TJ * 65) * 4;   // 66560 B
    static bool attr_set = false;
    if (!attr_set) {
        cudaFuncSetAttribute(dist_kernel,
                             cudaFuncAttributeMaxDynamicSharedMemorySize,
                             dist_smem);
        attr_set = true;
    }

    dist_kernel<<<dim3(MM / TJ, NN / TI, BQ), 256, dist_smem>>>(X, Y);
    dp_kernel<<<BQ, 256>>>(X_len, Y_len, out);
}